// round 1
// baseline (speedup 1.0000x reference)
#include <cuda_runtime.h>
#include <cuda_bf16.h>
#include <math.h>

// ============================================================================
// MultiheadAttention: out = proj( scramble( attn( proj(q), proj(k), proj(v) ) ) )
// proj(x) = x @ W^T + b,  N=8, S=1024, D=1024, H=16, d=64
// scramble: x[n][h][s][d] -> Z[h>>1][(h&1)*512 + n*64 + (s>>4)][(s&15)*64 + d]
// ============================================================================

#define D_MODEL 1024
#define SEQ     1024
#define NBATCH  8
#define NHEADS  16
#define HDIM    64
#define MROWS   (NBATCH * SEQ)   // 8192

// Scratch: Q, K, V, Z — 4 x 8M floats = 128 MB static device memory (allowed)
__device__ float g_scratch[4u * 8u * 1024u * 1024u];

// ----------------------------------------------------------------------------
// SGEMM: Y[M x 1024] = X[M x 1024] @ W[1024 x 1024]^T + bias
// 64x64 tile, BK=16, 256 threads, 4x4 microtile, k-major smem (+4 pad)
// ----------------------------------------------------------------------------
__global__ __launch_bounds__(256) void gemm_xwT_bias(
    const float* __restrict__ X, const float* __restrict__ W,
    const float* __restrict__ bias, float* __restrict__ Y)
{
    __shared__ float As[16][68];  // [k][m]
    __shared__ float Bs[16][68];  // [k][n]

    const int tid = threadIdx.x;
    const int tx = tid & 15;
    const int ty = tid >> 4;
    const int m0 = blockIdx.y * 64;
    const int n0 = blockIdx.x * 64;

    float acc[4][4] = {};

    for (int k0 = 0; k0 < D_MODEL; k0 += 16) {
        #pragma unroll
        for (int l = tid; l < 64 * 16; l += 256) {
            int r = l >> 4;
            int c = l & 15;
            As[c][r] = X[(size_t)(m0 + r) * D_MODEL + k0 + c];
            Bs[c][r] = W[(size_t)(n0 + r) * D_MODEL + k0 + c];
        }
        __syncthreads();

        #pragma unroll
        for (int kk = 0; kk < 16; kk++) {
            float4 a = *(const float4*)&As[kk][4 * ty];
            float4 b = *(const float4*)&Bs[kk][4 * tx];
            acc[0][0] += a.x * b.x; acc[0][1] += a.x * b.y; acc[0][2] += a.x * b.z; acc[0][3] += a.x * b.w;
            acc[1][0] += a.y * b.x; acc[1][1] += a.y * b.y; acc[1][2] += a.y * b.z; acc[1][3] += a.y * b.w;
            acc[2][0] += a.z * b.x; acc[2][1] += a.z * b.y; acc[2][2] += a.z * b.z; acc[2][3] += a.z * b.w;
            acc[3][0] += a.w * b.x; acc[3][1] += a.w * b.y; acc[3][2] += a.w * b.z; acc[3][3] += a.w * b.w;
        }
        __syncthreads();
    }

    #pragma unroll
    for (int i = 0; i < 4; i++) {
        int m = m0 + 4 * ty + i;
        #pragma unroll
        for (int j = 0; j < 4; j++) {
            int nn = n0 + 4 * tx + j;
            Y[(size_t)m * D_MODEL + nn] = acc[i][j] + bias[nn];
        }
    }
}

// ----------------------------------------------------------------------------
// Flash attention per (n, h, q-tile of 64), with reference's masked -1e9
// softmax and the scrambled head-merge written directly into Z.
// Dynamic smem layout (floats, rows padded to 68 for bank/alignment):
//   Qs[64][68] (d-major), Ks[64][68] (d-major), Vs[64][68] (k-major),
//   Ps[64][68], Ms[64][64] (int)
// ----------------------------------------------------------------------------
#define SMEM_ATTN ((4 * 64 * 68) * 4 + 64 * 64 * 4)

__global__ __launch_bounds__(256) void attn_kernel(
    const float* __restrict__ Q, const float* __restrict__ K,
    const float* __restrict__ V, const int* __restrict__ mask,
    float* __restrict__ Z)
{
    extern __shared__ float sm[];
    float* Qs = sm;               // Qs[d*68 + r]
    float* Ks = Qs + 64 * 68;     // Ks[d*68 + c]
    float* Vs = Ks + 64 * 68;     // Vs[k*68 + d]
    float* Ps = Vs + 64 * 68;     // Ps[r*68 + c]
    int*   Ms = (int*)(Ps + 64 * 68);  // Ms[r*64 + c]

    const int tid = threadIdx.x;
    const int tx = tid & 15;
    const int ty = tid >> 4;
    const int q0 = blockIdx.x * 64;
    const int h  = blockIdx.y;
    const int n  = blockIdx.z;

    const float* Qb = Q + (size_t)n * SEQ * D_MODEL + h * HDIM;
    const float* Kb = K + (size_t)n * SEQ * D_MODEL + h * HDIM;
    const float* Vb = V + (size_t)n * SEQ * D_MODEL + h * HDIM;
    const int*   Mb = mask + n * SEQ * SEQ;

    // Load Q tile (pre-scaled by 1/sqrt(64))
    #pragma unroll
    for (int l = tid; l < 64 * 64; l += 256) {
        int r = l >> 6, d = l & 63;
        Qs[d * 68 + r] = Qb[(size_t)(q0 + r) * D_MODEL + d] * 0.125f;
    }

    float o[4][4] = {};
    float rmax[4] = {-1e30f, -1e30f, -1e30f, -1e30f};
    float rsum[4] = {};

    for (int kt = 0; kt < 16; kt++) {
        const int k0 = kt * 64;
        __syncthreads();   // previous iter's Ks/Vs/Ps consumers done

        #pragma unroll
        for (int l = tid; l < 64 * 64; l += 256) {
            int r = l >> 6, d = l & 63;
            Ks[d * 68 + r] = Kb[(size_t)(k0 + r) * D_MODEL + d];
            Vs[r * 68 + d] = Vb[(size_t)(k0 + r) * D_MODEL + d];
            Ms[l]          = Mb[(size_t)(q0 + r) * SEQ + k0 + d];  // r=q-row, d=k-col
        }
        __syncthreads();

        // S = Qs @ Ks^T (already scaled)
        float s[4][4] = {};
        #pragma unroll 8
        for (int d = 0; d < 64; d++) {
            float4 a = *(const float4*)&Qs[d * 68 + 4 * ty];
            float4 b = *(const float4*)&Ks[d * 68 + 4 * tx];
            s[0][0] += a.x * b.x; s[0][1] += a.x * b.y; s[0][2] += a.x * b.z; s[0][3] += a.x * b.w;
            s[1][0] += a.y * b.x; s[1][1] += a.y * b.y; s[1][2] += a.y * b.z; s[1][3] += a.y * b.w;
            s[2][0] += a.z * b.x; s[2][1] += a.z * b.y; s[2][2] += a.z * b.z; s[2][3] += a.z * b.w;
            s[3][0] += a.w * b.x; s[3][1] += a.w * b.y; s[3][2] += a.w * b.z; s[3][3] += a.w * b.w;
        }

        // mask + online softmax per owned row
        #pragma unroll
        for (int i = 0; i < 4; i++) {
            const int r = 4 * ty + i;
            #pragma unroll
            for (int j = 0; j < 4; j++)
                if (Ms[r * 64 + 4 * tx + j] == 0) s[i][j] = -1e9f;

            float tm = fmaxf(fmaxf(s[i][0], s[i][1]), fmaxf(s[i][2], s[i][3]));
            #pragma unroll
            for (int off = 1; off < 16; off <<= 1)
                tm = fmaxf(tm, __shfl_xor_sync(0xffffffffu, tm, off));

            float mnew = fmaxf(rmax[i], tm);
            float corr = __expf(rmax[i] - mnew);

            float psum = 0.0f;
            #pragma unroll
            for (int j = 0; j < 4; j++) {
                float p = __expf(s[i][j] - mnew);
                Ps[r * 68 + 4 * tx + j] = p;
                psum += p;
            }
            #pragma unroll
            for (int off = 1; off < 16; off <<= 1)
                psum += __shfl_xor_sync(0xffffffffu, psum, off);

            rsum[i] = rsum[i] * corr + psum;
            rmax[i] = mnew;
            #pragma unroll
            for (int j = 0; j < 4; j++) o[i][j] *= corr;
        }
        __syncthreads();   // Ps visible to all

        // O += P @ V
        #pragma unroll 8
        for (int k = 0; k < 64; k++) {
            float4 b = *(const float4*)&Vs[k * 68 + 4 * tx];
            float a0 = Ps[(4 * ty + 0) * 68 + k];
            float a1 = Ps[(4 * ty + 1) * 68 + k];
            float a2 = Ps[(4 * ty + 2) * 68 + k];
            float a3 = Ps[(4 * ty + 3) * 68 + k];
            o[0][0] += a0 * b.x; o[0][1] += a0 * b.y; o[0][2] += a0 * b.z; o[0][3] += a0 * b.w;
            o[1][0] += a1 * b.x; o[1][1] += a1 * b.y; o[1][2] += a1 * b.z; o[1][3] += a1 * b.w;
            o[2][0] += a2 * b.x; o[2][1] += a2 * b.y; o[2][2] += a2 * b.z; o[2][3] += a2 * b.w;
            o[3][0] += a3 * b.x; o[3][1] += a3 * b.y; o[3][2] += a3 * b.z; o[3][3] += a3 * b.w;
        }
    }

    // Epilogue: divide by row sum, write to scrambled Z position
    #pragma unroll
    for (int i = 0; i < 4; i++) {
        const int sg  = q0 + 4 * ty + i;
        const float inv = 1.0f / rsum[i];
        const int bI = h >> 1;
        const int t  = ((h & 1) << 9) + (n << 6) + (sg >> 4);
        const int cb = ((sg & 15) << 6) + 4 * tx;
        float* Zp = Z + ((size_t)(bI * SEQ + t)) * D_MODEL + cb;
        #pragma unroll
        for (int j = 0; j < 4; j++) Zp[j] = o[i][j] * inv;
    }
}

// ----------------------------------------------------------------------------
// Launch
// ----------------------------------------------------------------------------
extern "C" void kernel_launch(void* const* d_in, const int* in_sizes, int n_in,
                              void* d_out, int out_size)
{
    const float* q    = (const float*)d_in[0];
    const float* k    = (const float*)d_in[1];
    const float* v    = (const float*)d_in[2];
    const int*   mask = (const int*)d_in[3];
    const float* W    = (const float*)d_in[4];
    const float* bias = (const float*)d_in[5];
    float* out = (float*)d_out;

    void* sp = nullptr;
    cudaGetSymbolAddress(&sp, g_scratch);
    float* Qp = (float*)sp;
    float* Kp = Qp + (size_t)8 * 1024 * 1024;
    float* Vp = Kp + (size_t)8 * 1024 * 1024;
    float* Zp = Vp + (size_t)8 * 1024 * 1024;

    cudaFuncSetAttribute(attn_kernel, cudaFuncAttributeMaxDynamicSharedMemorySize, SMEM_ATTN);

    dim3 ggrid(D_MODEL / 64, MROWS / 64);   // (16, 128)
    gemm_xwT_bias<<<ggrid, 256>>>(q, W, bias, Qp);
    gemm_xwT_bias<<<ggrid, 256>>>(k, W, bias, Kp);
    gemm_xwT_bias<<<ggrid, 256>>>(v, W, bias, Vp);

    attn_kernel<<<dim3(SEQ / 64, NHEADS, NBATCH), 256, SMEM_ATTN>>>(Qp, Kp, Vp, mask, Zp);

    gemm_xwT_bias<<<ggrid, 256>>>(Zp, W, bias, out);
}

// round 2
// speedup vs baseline: 1.7539x; 1.7539x over previous
#include <cuda_runtime.h>
#include <cuda_bf16.h>
#include <math.h>

// ============================================================================
// MultiheadAttention: out = proj( scramble( attn( proj(q), proj(k), proj(v) ) ) )
// proj(x) = x @ W^T + b,  N=8, S=1024, D=1024, H=16, d=64
// scramble: x[n][h][s][d] -> Z[h>>1][(h&1)*512 + n*64 + (s>>4)][(s&15)*64 + d]
// Round 2: projections moved to tf32 tensor-core MMA (m16n8k8).
// ============================================================================

#define D_MODEL 1024
#define SEQ     1024
#define NBATCH  8
#define NHEADS  16
#define HDIM    64
#define MROWS   (NBATCH * SEQ)   // 8192

// Scratch: Q, K, V, Z — 4 x 8M floats = 128 MB static device memory (allowed)
__device__ float g_scratch[4u * 8u * 1024u * 1024u];

// ----------------------------------------------------------------------------
// tf32 helpers
// ----------------------------------------------------------------------------
__device__ __forceinline__ unsigned tf32_rna(float f) {
    unsigned u;
    asm("cvt.rna.tf32.f32 %0, %1;" : "=r"(u) : "f"(f));
    return u;
}

__device__ __forceinline__ void mma_tf32(
    float& d0, float& d1, float& d2, float& d3,
    unsigned a0, unsigned a1, unsigned a2, unsigned a3,
    unsigned b0, unsigned b1)
{
    asm volatile(
        "mma.sync.aligned.m16n8k8.row.col.f32.tf32.tf32.f32 "
        "{%0,%1,%2,%3}, {%4,%5,%6,%7}, {%8,%9}, {%0,%1,%2,%3};"
        : "+f"(d0), "+f"(d1), "+f"(d2), "+f"(d3)
        : "r"(a0), "r"(a1), "r"(a2), "r"(a3), "r"(b0), "r"(b1));
}

// ----------------------------------------------------------------------------
// tf32 GEMM: Y[M x 1024] = X[M x 1024] @ W[1024 x 1024]^T + bias
// 128x128 tile, BK=16, 256 threads (8 warps, 2x4), warp tile 64x32.
// Smem padded to stride 20 -> conflict-free fragment loads.
// ----------------------------------------------------------------------------
#define BM 128
#define BN 128
#define BK 16
#define SSTR 20   // smem row stride (floats)

__global__ __launch_bounds__(256) void gemm_tf32_xwT_bias(
    const float* __restrict__ X, const float* __restrict__ W,
    const float* __restrict__ bias, float* __restrict__ Y)
{
    __shared__ unsigned As[BM][SSTR];  // [m][k]  (tf32 bits)
    __shared__ unsigned Bs[BN][SSTR];  // [n][k]  (tf32 bits)

    const int tid   = threadIdx.x;
    const int lane  = tid & 31;
    const int warp  = tid >> 5;
    const int warpM = warp >> 2;      // 0..1
    const int warpN = warp & 3;       // 0..3
    const int g     = lane >> 2;      // group id 0..7
    const int t     = lane & 3;       // thread-in-group 0..3

    const int m0 = blockIdx.y * BM;
    const int n0 = blockIdx.x * BN;

    float acc[4][4][4] = {};          // [mt][nt][4]

    // Staging: 512 float4 per matrix / 256 threads = 2 each
    const int srow0 = tid >> 1;            // 0..127 (two float4 per row scheme)
    // simpler: linear index l = tid + 256*i ; row = l>>2, f4 = l&3

    for (int k0 = 0; k0 < D_MODEL; k0 += BK) {
        #pragma unroll
        for (int i = 0; i < 2; i++) {
            int l   = tid + 256 * i;
            int r   = l >> 2;
            int f4  = l & 3;
            float4 xa = *(const float4*)&X[(size_t)(m0 + r) * D_MODEL + k0 + f4 * 4];
            float4 wb = *(const float4*)&W[(size_t)(n0 + r) * D_MODEL + k0 + f4 * 4];
            As[r][f4 * 4 + 0] = tf32_rna(xa.x);
            As[r][f4 * 4 + 1] = tf32_rna(xa.y);
            As[r][f4 * 4 + 2] = tf32_rna(xa.z);
            As[r][f4 * 4 + 3] = tf32_rna(xa.w);
            Bs[r][f4 * 4 + 0] = tf32_rna(wb.x);
            Bs[r][f4 * 4 + 1] = tf32_rna(wb.y);
            Bs[r][f4 * 4 + 2] = tf32_rna(wb.z);
            Bs[r][f4 * 4 + 3] = tf32_rna(wb.w);
        }
        __syncthreads();

        #pragma unroll
        for (int kk = 0; kk < 2; kk++) {
            const int kc = kk * 8;
            unsigned a[4][4], b[4][2];
            #pragma unroll
            for (int mt = 0; mt < 4; mt++) {
                const int mr = warpM * 64 + mt * 16 + g;
                a[mt][0] = As[mr    ][kc + t    ];
                a[mt][1] = As[mr + 8][kc + t    ];
                a[mt][2] = As[mr    ][kc + t + 4];
                a[mt][3] = As[mr + 8][kc + t + 4];
            }
            #pragma unroll
            for (int nt = 0; nt < 4; nt++) {
                const int nr = warpN * 32 + nt * 8 + g;
                b[nt][0] = Bs[nr][kc + t    ];
                b[nt][1] = Bs[nr][kc + t + 4];
            }
            #pragma unroll
            for (int mt = 0; mt < 4; mt++)
                #pragma unroll
                for (int nt = 0; nt < 4; nt++)
                    mma_tf32(acc[mt][nt][0], acc[mt][nt][1],
                             acc[mt][nt][2], acc[mt][nt][3],
                             a[mt][0], a[mt][1], a[mt][2], a[mt][3],
                             b[nt][0], b[nt][1]);
        }
        __syncthreads();
    }

    // Epilogue: c0 at (g, 2t), c1 (g, 2t+1), c2/c3 at row g+8
    #pragma unroll
    for (int mt = 0; mt < 4; mt++) {
        const int m = m0 + warpM * 64 + mt * 16 + g;
        #pragma unroll
        for (int nt = 0; nt < 4; nt++) {
            const int n = n0 + warpN * 32 + nt * 8 + 2 * t;
            float2 bv = *(const float2*)&bias[n];
            float2 r0 = make_float2(acc[mt][nt][0] + bv.x, acc[mt][nt][1] + bv.y);
            float2 r1 = make_float2(acc[mt][nt][2] + bv.x, acc[mt][nt][3] + bv.y);
            *(float2*)&Y[(size_t)m * D_MODEL + n]       = r0;
            *(float2*)&Y[(size_t)(m + 8) * D_MODEL + n] = r1;
        }
    }
}

// ----------------------------------------------------------------------------
// Flash attention per (n, h, q-tile of 64) — unchanged from round 1.
// ----------------------------------------------------------------------------
#define SMEM_ATTN ((4 * 64 * 68) * 4 + 64 * 64 * 4)

__global__ __launch_bounds__(256) void attn_kernel(
    const float* __restrict__ Q, const float* __restrict__ K,
    const float* __restrict__ V, const int* __restrict__ mask,
    float* __restrict__ Z)
{
    extern __shared__ float sm[];
    float* Qs = sm;               // Qs[d*68 + r]
    float* Ks = Qs + 64 * 68;     // Ks[d*68 + c]
    float* Vs = Ks + 64 * 68;     // Vs[k*68 + d]
    float* Ps = Vs + 64 * 68;     // Ps[r*68 + c]
    int*   Ms = (int*)(Ps + 64 * 68);  // Ms[r*64 + c]

    const int tid = threadIdx.x;
    const int tx = tid & 15;
    const int ty = tid >> 4;
    const int q0 = blockIdx.x * 64;
    const int h  = blockIdx.y;
    const int n  = blockIdx.z;

    const float* Qb = Q + (size_t)n * SEQ * D_MODEL + h * HDIM;
    const float* Kb = K + (size_t)n * SEQ * D_MODEL + h * HDIM;
    const float* Vb = V + (size_t)n * SEQ * D_MODEL + h * HDIM;
    const int*   Mb = mask + n * SEQ * SEQ;

    #pragma unroll
    for (int l = tid; l < 64 * 64; l += 256) {
        int r = l >> 6, d = l & 63;
        Qs[d * 68 + r] = Qb[(size_t)(q0 + r) * D_MODEL + d] * 0.125f;
    }

    float o[4][4] = {};
    float rmax[4] = {-1e30f, -1e30f, -1e30f, -1e30f};
    float rsum[4] = {};

    for (int kt = 0; kt < 16; kt++) {
        const int k0 = kt * 64;
        __syncthreads();

        #pragma unroll
        for (int l = tid; l < 64 * 64; l += 256) {
            int r = l >> 6, d = l & 63;
            Ks[d * 68 + r] = Kb[(size_t)(k0 + r) * D_MODEL + d];
            Vs[r * 68 + d] = Vb[(size_t)(k0 + r) * D_MODEL + d];
            Ms[l]          = Mb[(size_t)(q0 + r) * SEQ + k0 + d];
        }
        __syncthreads();

        float s[4][4] = {};
        #pragma unroll 8
        for (int d = 0; d < 64; d++) {
            float4 a = *(const float4*)&Qs[d * 68 + 4 * ty];
            float4 b = *(const float4*)&Ks[d * 68 + 4 * tx];
            s[0][0] += a.x * b.x; s[0][1] += a.x * b.y; s[0][2] += a.x * b.z; s[0][3] += a.x * b.w;
            s[1][0] += a.y * b.x; s[1][1] += a.y * b.y; s[1][2] += a.y * b.z; s[1][3] += a.y * b.w;
            s[2][0] += a.z * b.x; s[2][1] += a.z * b.y; s[2][2] += a.z * b.z; s[2][3] += a.z * b.w;
            s[3][0] += a.w * b.x; s[3][1] += a.w * b.y; s[3][2] += a.w * b.z; s[3][3] += a.w * b.w;
        }

        #pragma unroll
        for (int i = 0; i < 4; i++) {
            const int r = 4 * ty + i;
            #pragma unroll
            for (int j = 0; j < 4; j++)
                if (Ms[r * 64 + 4 * tx + j] == 0) s[i][j] = -1e9f;

            float tm = fmaxf(fmaxf(s[i][0], s[i][1]), fmaxf(s[i][2], s[i][3]));
            #pragma unroll
            for (int off = 1; off < 16; off <<= 1)
                tm = fmaxf(tm, __shfl_xor_sync(0xffffffffu, tm, off));

            float mnew = fmaxf(rmax[i], tm);
            float corr = __expf(rmax[i] - mnew);

            float psum = 0.0f;
            #pragma unroll
            for (int j = 0; j < 4; j++) {
                float p = __expf(s[i][j] - mnew);
                Ps[r * 68 + 4 * tx + j] = p;
                psum += p;
            }
            #pragma unroll
            for (int off = 1; off < 16; off <<= 1)
                psum += __shfl_xor_sync(0xffffffffu, psum, off);

            rsum[i] = rsum[i] * corr + psum;
            rmax[i] = mnew;
            #pragma unroll
            for (int j = 0; j < 4; j++) o[i][j] *= corr;
        }
        __syncthreads();

        #pragma unroll 8
        for (int k = 0; k < 64; k++) {
            float4 b = *(const float4*)&Vs[k * 68 + 4 * tx];
            float a0 = Ps[(4 * ty + 0) * 68 + k];
            float a1 = Ps[(4 * ty + 1) * 68 + k];
            float a2 = Ps[(4 * ty + 2) * 68 + k];
            float a3 = Ps[(4 * ty + 3) * 68 + k];
            o[0][0] += a0 * b.x; o[0][1] += a0 * b.y; o[0][2] += a0 * b.z; o[0][3] += a0 * b.w;
            o[1][0] += a1 * b.x; o[1][1] += a1 * b.y; o[1][2] += a1 * b.z; o[1][3] += a1 * b.w;
            o[2][0] += a2 * b.x; o[2][1] += a2 * b.y; o[2][2] += a2 * b.z; o[2][3] += a2 * b.w;
            o[3][0] += a3 * b.x; o[3][1] += a3 * b.y; o[3][2] += a3 * b.z; o[3][3] += a3 * b.w;
        }
    }

    #pragma unroll
    for (int i = 0; i < 4; i++) {
        const int sg  = q0 + 4 * ty + i;
        const float inv = 1.0f / rsum[i];
        const int bI = h >> 1;
        const int t2 = ((h & 1) << 9) + (n << 6) + (sg >> 4);
        const int cb = ((sg & 15) << 6) + 4 * tx;
        float* Zp = Z + ((size_t)(bI * SEQ + t2)) * D_MODEL + cb;
        #pragma unroll
        for (int j = 0; j < 4; j++) Zp[j] = o[i][j] * inv;
    }
}

// ----------------------------------------------------------------------------
// Launch
// ----------------------------------------------------------------------------
extern "C" void kernel_launch(void* const* d_in, const int* in_sizes, int n_in,
                              void* d_out, int out_size)
{
    const float* q    = (const float*)d_in[0];
    const float* k    = (const float*)d_in[1];
    const float* v    = (const float*)d_in[2];
    const int*   mask = (const int*)d_in[3];
    const float* W    = (const float*)d_in[4];
    const float* bias = (const float*)d_in[5];
    float* out = (float*)d_out;

    void* sp = nullptr;
    cudaGetSymbolAddress(&sp, g_scratch);
    float* Qp = (float*)sp;
    float* Kp = Qp + (size_t)8 * 1024 * 1024;
    float* Vp = Kp + (size_t)8 * 1024 * 1024;
    float* Zp = Vp + (size_t)8 * 1024 * 1024;

    cudaFuncSetAttribute(attn_kernel, cudaFuncAttributeMaxDynamicSharedMemorySize, SMEM_ATTN);

    dim3 ggrid(D_MODEL / BN, MROWS / BM);   // (8, 64)
    gemm_tf32_xwT_bias<<<ggrid, 256>>>(q, W, bias, Qp);
    gemm_tf32_xwT_bias<<<ggrid, 256>>>(k, W, bias, Kp);
    gemm_tf32_xwT_bias<<<ggrid, 256>>>(v, W, bias, Vp);

    attn_kernel<<<dim3(SEQ / 64, NHEADS, NBATCH), 256, SMEM_ATTN>>>(Qp, Kp, Vp, mask, Zp);

    gemm_tf32_xwT_bias<<<ggrid, 256>>>(Zp, W, bias, out);
}

// round 3
// speedup vs baseline: 2.7668x; 1.5774x over previous
#include <cuda_runtime.h>
#include <cuda_bf16.h>
#include <math.h>

// ============================================================================
// MultiheadAttention: out = proj( scramble( attn( proj(q), proj(k), proj(v) ) ) )
// proj(x) = x @ W^T + b,  N=8, S=1024, D=1024, H=16, d=64
// scramble: x[n][h][s][d] -> Z[h>>1][(h&1)*512 + n*64 + (s>>4)][(s&15)*64 + d]
// Round 3: attention matmuls moved to tf32 MMA; mask bit-packed.
// ============================================================================

#define D_MODEL 1024
#define SEQ     1024
#define NBATCH  8
#define NHEADS  16
#define HDIM    64
#define MROWS   (NBATCH * SEQ)   // 8192

__device__ float g_scratch[4u * 8u * 1024u * 1024u];            // Q,K,V,Z (128 MB)
__device__ unsigned long long g_pm[(size_t)MROWS * 16];          // packed mask bits (1 MB)

// ----------------------------------------------------------------------------
// tf32 helpers (validated in round 2)
// ----------------------------------------------------------------------------
__device__ __forceinline__ unsigned tf32_rna(float f) {
    unsigned u;
    asm("cvt.rna.tf32.f32 %0, %1;" : "=r"(u) : "f"(f));
    return u;
}

__device__ __forceinline__ void mma_tf32(
    float& d0, float& d1, float& d2, float& d3,
    unsigned a0, unsigned a1, unsigned a2, unsigned a3,
    unsigned b0, unsigned b1)
{
    asm volatile(
        "mma.sync.aligned.m16n8k8.row.col.f32.tf32.tf32.f32 "
        "{%0,%1,%2,%3}, {%4,%5,%6,%7}, {%8,%9}, {%0,%1,%2,%3};"
        : "+f"(d0), "+f"(d1), "+f"(d2), "+f"(d3)
        : "r"(a0), "r"(a1), "r"(a2), "r"(a3), "r"(b0), "r"(b1));
}

// ----------------------------------------------------------------------------
// Mask prepack: bit (n,q,k) -> g_pm[(n*S+q)*16 + k/64] bit k%64
// ----------------------------------------------------------------------------
__global__ __launch_bounds__(256) void pack_mask(const int* __restrict__ mask,
                                                 unsigned long long* __restrict__ PM)
{
    const int lane = threadIdx.x & 31;
    const int w    = threadIdx.x >> 5;
    const int row  = blockIdx.x * 8 + w;        // 1024 blocks x 8 warps = 8192 rows
    const int* mrow = mask + (size_t)row * SEQ;
    #pragma unroll
    for (int j = 0; j < 16; j++) {
        unsigned b0 = __ballot_sync(0xffffffffu, mrow[j * 64 + lane]      != 0);
        unsigned b1 = __ballot_sync(0xffffffffu, mrow[j * 64 + 32 + lane] != 0);
        if (lane == 0)
            PM[(size_t)row * 16 + j] = (unsigned long long)b0 |
                                       ((unsigned long long)b1 << 32);
    }
}

// ----------------------------------------------------------------------------
// tf32 GEMM (unchanged from round 2): Y = X @ W^T + bias
// ----------------------------------------------------------------------------
#define BM 128
#define BN 128
#define BK 16
#define SSTR 20

__global__ __launch_bounds__(256) void gemm_tf32_xwT_bias(
    const float* __restrict__ X, const float* __restrict__ W,
    const float* __restrict__ bias, float* __restrict__ Y)
{
    __shared__ unsigned As[BM][SSTR];
    __shared__ unsigned Bs[BN][SSTR];

    const int tid   = threadIdx.x;
    const int lane  = tid & 31;
    const int warp  = tid >> 5;
    const int warpM = warp >> 2;
    const int warpN = warp & 3;
    const int g     = lane >> 2;
    const int t     = lane & 3;

    const int m0 = blockIdx.y * BM;
    const int n0 = blockIdx.x * BN;

    float acc[4][4][4] = {};

    for (int k0 = 0; k0 < D_MODEL; k0 += BK) {
        #pragma unroll
        for (int i = 0; i < 2; i++) {
            int l   = tid + 256 * i;
            int r   = l >> 2;
            int f4  = l & 3;
            float4 xa = *(const float4*)&X[(size_t)(m0 + r) * D_MODEL + k0 + f4 * 4];
            float4 wb = *(const float4*)&W[(size_t)(n0 + r) * D_MODEL + k0 + f4 * 4];
            As[r][f4 * 4 + 0] = tf32_rna(xa.x);
            As[r][f4 * 4 + 1] = tf32_rna(xa.y);
            As[r][f4 * 4 + 2] = tf32_rna(xa.z);
            As[r][f4 * 4 + 3] = tf32_rna(xa.w);
            Bs[r][f4 * 4 + 0] = tf32_rna(wb.x);
            Bs[r][f4 * 4 + 1] = tf32_rna(wb.y);
            Bs[r][f4 * 4 + 2] = tf32_rna(wb.z);
            Bs[r][f4 * 4 + 3] = tf32_rna(wb.w);
        }
        __syncthreads();

        #pragma unroll
        for (int kk = 0; kk < 2; kk++) {
            const int kc = kk * 8;
            unsigned a[4][4], b[4][2];
            #pragma unroll
            for (int mt = 0; mt < 4; mt++) {
                const int mr = warpM * 64 + mt * 16 + g;
                a[mt][0] = As[mr    ][kc + t    ];
                a[mt][1] = As[mr + 8][kc + t    ];
                a[mt][2] = As[mr    ][kc + t + 4];
                a[mt][3] = As[mr + 8][kc + t + 4];
            }
            #pragma unroll
            for (int nt = 0; nt < 4; nt++) {
                const int nr = warpN * 32 + nt * 8 + g;
                b[nt][0] = Bs[nr][kc + t    ];
                b[nt][1] = Bs[nr][kc + t + 4];
            }
            #pragma unroll
            for (int mt = 0; mt < 4; mt++)
                #pragma unroll
                for (int nt = 0; nt < 4; nt++)
                    mma_tf32(acc[mt][nt][0], acc[mt][nt][1],
                             acc[mt][nt][2], acc[mt][nt][3],
                             a[mt][0], a[mt][1], a[mt][2], a[mt][3],
                             b[nt][0], b[nt][1]);
        }
        __syncthreads();
    }

    #pragma unroll
    for (int mt = 0; mt < 4; mt++) {
        const int m = m0 + warpM * 64 + mt * 16 + g;
        #pragma unroll
        for (int nt = 0; nt < 4; nt++) {
            const int n = n0 + warpN * 32 + nt * 8 + 2 * t;
            float2 bv = *(const float2*)&bias[n];
            float2 r0 = make_float2(acc[mt][nt][0] + bv.x, acc[mt][nt][1] + bv.y);
            float2 r1 = make_float2(acc[mt][nt][2] + bv.x, acc[mt][nt][3] + bv.y);
            *(float2*)&Y[(size_t)m * D_MODEL + n]       = r0;
            *(float2*)&Y[(size_t)(m + 8) * D_MODEL + n] = r1;
        }
    }
}

// ----------------------------------------------------------------------------
// Tensor-core flash attention. 128 threads = 4 warps; warp w owns q-rows
// [q0 + 16w, q0 + 16w + 16). Smem (tf32 bits): Ks[64][68], Vs[64][68],
// Ps[4 warps][16][68].
// ----------------------------------------------------------------------------
#define ASTR 68
#define SMEM_ATTN ((64 + 64 + 64) * ASTR * 4)   // 52224 B

__global__ __launch_bounds__(128) void attn_tc(
    const float* __restrict__ Q, const float* __restrict__ K,
    const float* __restrict__ V, const unsigned long long* __restrict__ PM,
    float* __restrict__ Z)
{
    extern __shared__ unsigned smu[];
    unsigned* Ks = smu;                         // [key][d]
    unsigned* Vs = Ks + 64 * ASTR;              // [key][d]
    unsigned* Psw = Vs + 64 * ASTR + (threadIdx.x >> 5) * 16 * ASTR;  // warp-private [16][ASTR]

    const int tid  = threadIdx.x;
    const int lane = tid & 31;
    const int w    = tid >> 5;
    const int g    = lane >> 2;
    const int t    = lane & 3;
    const int q0   = blockIdx.x * 64;
    const int h    = blockIdx.y;
    const int n    = blockIdx.z;

    const float* Qb = Q + (size_t)n * SEQ * D_MODEL + h * HDIM;
    const float* Kb = K + (size_t)n * SEQ * D_MODEL + h * HDIM;
    const float* Vb = V + (size_t)n * SEQ * D_MODEL + h * HDIM;
    const unsigned long long* Mb = PM + ((size_t)n * SEQ + q0) * 16;

    // Q fragments (scaled by 1/sqrt(64), exact power of 2)
    const int qr = q0 + w * 16 + g;
    unsigned aq[8][4];
    #pragma unroll
    for (int ks = 0; ks < 8; ks++) {
        aq[ks][0] = tf32_rna(Qb[(size_t)qr       * D_MODEL + ks * 8 + t    ] * 0.125f);
        aq[ks][1] = tf32_rna(Qb[(size_t)(qr + 8) * D_MODEL + ks * 8 + t    ] * 0.125f);
        aq[ks][2] = tf32_rna(Qb[(size_t)qr       * D_MODEL + ks * 8 + t + 4] * 0.125f);
        aq[ks][3] = tf32_rna(Qb[(size_t)(qr + 8) * D_MODEL + ks * 8 + t + 4] * 0.125f);
    }

    float o[8][4] = {};
    float mx_lo = -1e30f, mx_hi = -1e30f;
    float sum_lo = 0.0f, sum_hi = 0.0f;

    for (int kt = 0; kt < 16; kt++) {
        const int k0 = kt * 64;
        __syncthreads();
        // Stage K/V tile (64x64) as tf32: 1024 float4 per matrix / 128 thr = 8 each
        #pragma unroll
        for (int i = 0; i < 8; i++) {
            int lf  = tid + 128 * i;
            int r   = lf >> 4;
            int c4  = (lf & 15) * 4;
            float4 kv = *(const float4*)&Kb[(size_t)(k0 + r) * D_MODEL + c4];
            float4 vv = *(const float4*)&Vb[(size_t)(k0 + r) * D_MODEL + c4];
            Ks[r * ASTR + c4 + 0] = tf32_rna(kv.x);
            Ks[r * ASTR + c4 + 1] = tf32_rna(kv.y);
            Ks[r * ASTR + c4 + 2] = tf32_rna(kv.z);
            Ks[r * ASTR + c4 + 3] = tf32_rna(kv.w);
            Vs[r * ASTR + c4 + 0] = tf32_rna(vv.x);
            Vs[r * ASTR + c4 + 1] = tf32_rna(vv.y);
            Vs[r * ASTR + c4 + 2] = tf32_rna(vv.z);
            Vs[r * ASTR + c4 + 3] = tf32_rna(vv.w);
        }
        __syncthreads();

        const unsigned long long mlo = Mb[(size_t)(w * 16 + g)     * 16 + kt];
        const unsigned long long mhi = Mb[(size_t)(w * 16 + g + 8) * 16 + kt];

        // S = Q @ K^T  (64 q-rows x 64 keys; this warp: 16 x 64)
        float s[8][4] = {};
        #pragma unroll
        for (int ks = 0; ks < 8; ks++) {
            #pragma unroll
            for (int nt = 0; nt < 8; nt++) {
                unsigned b0 = Ks[(nt * 8 + g) * ASTR + ks * 8 + t    ];
                unsigned b1 = Ks[(nt * 8 + g) * ASTR + ks * 8 + t + 4];
                mma_tf32(s[nt][0], s[nt][1], s[nt][2], s[nt][3],
                         aq[ks][0], aq[ks][1], aq[ks][2], aq[ks][3], b0, b1);
            }
        }

        // mask + row max
        float tm_lo = -1e30f, tm_hi = -1e30f;
        #pragma unroll
        for (int nt = 0; nt < 8; nt++) {
            const int c = nt * 8 + 2 * t;
            if (!((mlo >> c) & 1ull))       s[nt][0] = -1e9f;
            if (!((mlo >> (c + 1)) & 1ull)) s[nt][1] = -1e9f;
            if (!((mhi >> c) & 1ull))       s[nt][2] = -1e9f;
            if (!((mhi >> (c + 1)) & 1ull)) s[nt][3] = -1e9f;
            tm_lo = fmaxf(tm_lo, fmaxf(s[nt][0], s[nt][1]));
            tm_hi = fmaxf(tm_hi, fmaxf(s[nt][2], s[nt][3]));
        }
        tm_lo = fmaxf(tm_lo, __shfl_xor_sync(0xffffffffu, tm_lo, 1));
        tm_lo = fmaxf(tm_lo, __shfl_xor_sync(0xffffffffu, tm_lo, 2));
        tm_hi = fmaxf(tm_hi, __shfl_xor_sync(0xffffffffu, tm_hi, 1));
        tm_hi = fmaxf(tm_hi, __shfl_xor_sync(0xffffffffu, tm_hi, 2));

        const float mn_lo = fmaxf(mx_lo, tm_lo);
        const float mn_hi = fmaxf(mx_hi, tm_hi);
        const float corr_lo = __expf(mx_lo - mn_lo);
        const float corr_hi = __expf(mx_hi - mn_hi);

        float ps_lo = 0.0f, ps_hi = 0.0f;
        #pragma unroll
        for (int nt = 0; nt < 8; nt++) {
            float p0 = __expf(s[nt][0] - mn_lo);
            float p1 = __expf(s[nt][1] - mn_lo);
            float p2 = __expf(s[nt][2] - mn_hi);
            float p3 = __expf(s[nt][3] - mn_hi);
            ps_lo += p0 + p1;
            ps_hi += p2 + p3;
            uint2 lo = make_uint2(tf32_rna(p0), tf32_rna(p1));
            uint2 hi = make_uint2(tf32_rna(p2), tf32_rna(p3));
            *(uint2*)&Psw[g       * ASTR + nt * 8 + 2 * t] = lo;
            *(uint2*)&Psw[(g + 8) * ASTR + nt * 8 + 2 * t] = hi;
        }
        ps_lo += __shfl_xor_sync(0xffffffffu, ps_lo, 1);
        ps_lo += __shfl_xor_sync(0xffffffffu, ps_lo, 2);
        ps_hi += __shfl_xor_sync(0xffffffffu, ps_hi, 1);
        ps_hi += __shfl_xor_sync(0xffffffffu, ps_hi, 2);

        sum_lo = sum_lo * corr_lo + ps_lo;
        sum_hi = sum_hi * corr_hi + ps_hi;
        mx_lo = mn_lo;
        mx_hi = mn_hi;
        #pragma unroll
        for (int nt = 0; nt < 8; nt++) {
            o[nt][0] *= corr_lo; o[nt][1] *= corr_lo;
            o[nt][2] *= corr_hi; o[nt][3] *= corr_hi;
        }
        __syncwarp();

        // O += P @ V  (16 x 64 += (16 x 64) @ (64 x 64))
        #pragma unroll
        for (int ks = 0; ks < 8; ks++) {
            unsigned ap0 = Psw[g       * ASTR + ks * 8 + t    ];
            unsigned ap1 = Psw[(g + 8) * ASTR + ks * 8 + t    ];
            unsigned ap2 = Psw[g       * ASTR + ks * 8 + t + 4];
            unsigned ap3 = Psw[(g + 8) * ASTR + ks * 8 + t + 4];
            #pragma unroll
            for (int nt = 0; nt < 8; nt++) {
                unsigned b0 = Vs[(ks * 8 + t    ) * ASTR + nt * 8 + g];
                unsigned b1 = Vs[(ks * 8 + t + 4) * ASTR + nt * 8 + g];
                mma_tf32(o[nt][0], o[nt][1], o[nt][2], o[nt][3],
                         ap0, ap1, ap2, ap3, b0, b1);
            }
        }
    }

    // Epilogue: normalize + scrambled store
    const float inv_lo = 1.0f / sum_lo;
    const float inv_hi = 1.0f / sum_hi;
    const int sg_lo = q0 + w * 16 + g;
    const int sg_hi = sg_lo + 8;
    const int bI = h >> 1;
    const int t2_lo = ((h & 1) << 9) + (n << 6) + (sg_lo >> 4);
    const int t2_hi = ((h & 1) << 9) + (n << 6) + (sg_hi >> 4);
    float* Zlo = Z + ((size_t)(bI * SEQ + t2_lo)) * D_MODEL + ((sg_lo & 15) << 6);
    float* Zhi = Z + ((size_t)(bI * SEQ + t2_hi)) * D_MODEL + ((sg_hi & 15) << 6);
    #pragma unroll
    for (int nt = 0; nt < 8; nt++) {
        const int d0 = nt * 8 + 2 * t;
        *(float2*)&Zlo[d0] = make_float2(o[nt][0] * inv_lo, o[nt][1] * inv_lo);
        *(float2*)&Zhi[d0] = make_float2(o[nt][2] * inv_hi, o[nt][3] * inv_hi);
    }
}

// ----------------------------------------------------------------------------
// Launch
// ----------------------------------------------------------------------------
extern "C" void kernel_launch(void* const* d_in, const int* in_sizes, int n_in,
                              void* d_out, int out_size)
{
    const float* q    = (const float*)d_in[0];
    const float* k    = (const float*)d_in[1];
    const float* v    = (const float*)d_in[2];
    const int*   mask = (const int*)d_in[3];
    const float* W    = (const float*)d_in[4];
    const float* bias = (const float*)d_in[5];
    float* out = (float*)d_out;

    void* sp = nullptr;
    cudaGetSymbolAddress(&sp, g_scratch);
    float* Qp = (float*)sp;
    float* Kp = Qp + (size_t)8 * 1024 * 1024;
    float* Vp = Kp + (size_t)8 * 1024 * 1024;
    float* Zp = Vp + (size_t)8 * 1024 * 1024;

    void* pmv = nullptr;
    cudaGetSymbolAddress(&pmv, g_pm);
    unsigned long long* PM = (unsigned long long*)pmv;

    cudaFuncSetAttribute(attn_tc, cudaFuncAttributeMaxDynamicSharedMemorySize, SMEM_ATTN);

    pack_mask<<<MROWS / 8, 256>>>(mask, PM);

    dim3 ggrid(D_MODEL / BN, MROWS / BM);   // (8, 64)
    gemm_tf32_xwT_bias<<<ggrid, 256>>>(q, W, bias, Qp);
    gemm_tf32_xwT_bias<<<ggrid, 256>>>(k, W, bias, Kp);
    gemm_tf32_xwT_bias<<<ggrid, 256>>>(v, W, bias, Vp);

    attn_tc<<<dim3(SEQ / 64, NHEADS, NBATCH), 128, SMEM_ATTN>>>(Qp, Kp, Vp, PM, Zp);

    gemm_tf32_xwT_bias<<<ggrid, 256>>>(Zp, W, bias, out);
}